// round 14
// baseline (speedup 1.0000x reference)
#include <cuda_runtime.h>

// Problem constants (fixed by the dataset)
#define NA 200000          // num authors
#define NP 500000          // num papers
#define NE 2000000         // num writes-edges
#define NL 500000          // num label edges
#define HID 128
#define SCAN_NB ((NA + 1023) / 1024)   // 196 blocks per scan
#define HALF (NP / 2)                  // paper-id split for L2 blocking

// ---------------- device scratch (static, no allocation) ----------------
__device__ float g_acc[(size_t)NA * HID];  // partial sums -> avg -> author_g
__device__ float g_ac[NA];                 // author_c scalar per author
__device__ float g_B[HID * HID];           // W_author @ W_paper^T
__device__ float g_M[HID * HID];           // W_paper @ B  (collapsed operator)
__device__ float g_u1[HID];
__device__ float g_u0[HID];
__device__ float g_v[HID];
__device__ float g_c1c0[2];

// edge sort (by author)
__device__ int g_acnt[NA];
__device__ int g_aoff[NA];
__device__ int g_acur[NA];
__device__ int g_sp[NE];

// label-edge sort (by author)
__device__ int g_lcnt[NA];
__device__ int g_loff[NA];
__device__ int g_lcur[NA];
__device__ int2 g_slab[NL];

// two-level scan temporaries (device-side access only!)
__device__ int g_bsA[512];
__device__ int g_bsL[512];

// ---------------- packed f32x2 helpers ----------------
__device__ __forceinline__ unsigned long long pack2(float lo, float hi) {
    unsigned long long r;
    asm("mov.b64 %0, {%1, %2};" : "=l"(r) : "f"(lo), "f"(hi));
    return r;
}
__device__ __forceinline__ void unpack2(unsigned long long v, float& lo, float& hi) {
    asm("mov.b64 {%0, %1}, %2;" : "=f"(lo), "=f"(hi) : "l"(v));
}
#define FMA_F32X2(d, a, b, c) \
    asm("fma.rn.f32x2 %0, %1, %2, %3;" : "=l"(d) : "l"(a), "l"(b), "l"(c))

// ---------------- L1: zero histograms + prep1 packed ----------------
#define ZERO_BLOCKS 512
__global__ void k_zero_prep1(const float* __restrict__ Wp, const float* __restrict__ Wa) {
    if (blockIdx.x < ZERO_BLOCKS) {
        int i = blockIdx.x * blockDim.x + threadIdx.x;
        int stride = ZERO_BLOCKS * blockDim.x;
        for (int j = i; j < NA; j += stride) { g_acnt[j] = 0; g_lcnt[j] = 0; }
    } else {
        __shared__ float wa[HID];
        int m = blockIdx.x - ZERO_BLOCKS;
        int j = threadIdx.x;
        if (j < HID) wa[j] = Wa[m * HID + j];
        __syncthreads();
        if (j < HID) {
            float s = 0.f;
#pragma unroll 8
            for (int k = 0; k < HID; k++) s += wa[k] * Wp[j * HID + k];
            g_B[m * HID + j] = s;
        }
    }
}

// ---------------- L2: hist + prep2 packed ----------------
__device__ void prep2_body(int bI, const float* __restrict__ Wp, const float* __restrict__ bp,
                           const float* __restrict__ Wa, const float* __restrict__ ba) {
    int j = threadIdx.x;
    if (bI < HID) {
        __shared__ float wp[HID];
        if (j < HID) wp[j] = Wp[bI * HID + j];
        __syncthreads();
        if (j < HID) {
            float s = 0.f;
#pragma unroll 8
            for (int m = 0; m < HID; m++) s += wp[m] * g_B[m * HID + j];
            g_M[bI * HID + j] = s;
        }
    } else {
        __shared__ float w[HID];
        if (j < HID) {
            float s = 0.f;
            for (int k = 0; k < HID; k++) s += Wa[j * HID + k] * bp[k];
            w[j] = s;
            float u0 = 0.f;
            for (int k = 0; k < HID; k++) u0 += ba[k] * Wp[j * HID + k];
            g_u0[j] = u0;
            float u1 = u0;
            for (int m = 0; m < HID; m++) u1 += bp[m] * g_B[m * HID + j];
            g_u1[j] = u1;
        }
        __syncthreads();
        if (j < HID) {
            float v = 0.f;
            for (int m = 0; m < HID; m++) v += Wp[j * HID + m] * w[m];
            g_v[j] = v;
            if (j == 0) {
                float c0 = 0.f;
                for (int k = 0; k < HID; k++) c0 += ba[k] * bp[k];
                float c1 = c0;
                for (int m = 0; m < HID; m++) c1 += bp[m] * w[m];
                g_c1c0[0] = c1;
                g_c1c0[1] = c0;
            }
        }
    }
}

#define HIST_BLOCKS 2048
__global__ void k_hist_prep2(const int* __restrict__ aid, const int* __restrict__ laid,
                             const float* __restrict__ Wp, const float* __restrict__ bp,
                             const float* __restrict__ Wa, const float* __restrict__ ba) {
    if (blockIdx.x < HIST_BLOCKS) {
        int i = blockIdx.x * blockDim.x + threadIdx.x;
        int stride = HIST_BLOCKS * blockDim.x;
        for (int e = i; e < NE; e += stride)
            atomicAdd(&g_acnt[__ldg(aid + e)], 1);
        for (int e = i; e < NL; e += stride)
            atomicAdd(&g_lcnt[__ldg(laid + e)], 1);
    } else {
        prep2_body(blockIdx.x - HIST_BLOCKS, Wp, bp, Wa, ba);
    }
}

// ---------------- L3: scan1 (per-block inclusive scan + block sums) ----------------
__device__ __forceinline__ void scan1_body(const int* __restrict__ in, int* __restrict__ out,
                                           int* __restrict__ bsum, int n) {
    __shared__ int s[1024];
    int i = blockIdx.x * 1024 + threadIdx.x;
    int v = (i < n) ? in[i] : 0;
    s[threadIdx.x] = v;
    __syncthreads();
    for (int o = 1; o < 1024; o <<= 1) {
        int t = (threadIdx.x >= o) ? s[threadIdx.x - o] : 0;
        __syncthreads();
        s[threadIdx.x] += t;
        __syncthreads();
    }
    if (i < n) out[i] = s[threadIdx.x] - v;
    if (threadIdx.x == 1023) bsum[blockIdx.x] = s[1023];
}

__global__ void k_scan1_both() {
    if (blockIdx.y == 0) scan1_body(g_acnt, g_aoff, g_bsA, NA);
    else                 scan1_body(g_lcnt, g_loff, g_bsL, NA);
}

// ---------------- L4: fused scan2+scan3 — each block re-scans block sums in smem ----
__device__ __forceinline__ void scan23_body(int* __restrict__ off, int* __restrict__ cur,
                                            const int* __restrict__ bsum, int n, int nb) {
    __shared__ int s[512];
    if (threadIdx.x < 512)
        s[threadIdx.x] = (threadIdx.x < nb) ? bsum[threadIdx.x] : 0;
    __syncthreads();
    for (int o = 1; o < 512; o <<= 1) {
        int t = (threadIdx.x < 512 && threadIdx.x >= o) ? s[threadIdx.x - o] : 0;
        __syncthreads();
        if (threadIdx.x < 512) s[threadIdx.x] += t;
        __syncthreads();
    }
    int bpre = (blockIdx.x == 0) ? 0 : s[blockIdx.x - 1];  // exclusive prefix of my block
    int i = blockIdx.x * 1024 + threadIdx.x;
    if (i < n) {
        int o2 = off[i] + bpre;
        off[i] = o2;
        cur[i] = o2;
    }
}

__global__ void k_scan23_both() {
    if (blockIdx.y == 0) scan23_body(g_aoff, g_acur, g_bsA, NA, SCAN_NB);
    else                 scan23_body(g_loff, g_lcur, g_bsL, NA, SCAN_NB);
}

// ---------------- L5: merged reorder ----------------
__global__ void k_reorder(const int* __restrict__ aid, const int* __restrict__ pid,
                          const int* __restrict__ laid, const int* __restrict__ lpid) {
    int i = blockIdx.x * blockDim.x + threadIdx.x;
    int stride = gridDim.x * blockDim.x;
    for (int e = i; e < NE; e += stride) {
        int a = __ldg(aid + e);
        int pos = atomicAdd(&g_acur[a], 1);
        g_sp[pos] = __ldg(pid + e);
    }
    for (int e = i; e < NL; e += stride) {
        int a = __ldg(laid + e);
        int pos = atomicAdd(&g_lcur[a], 1);
        g_slab[pos] = make_int2(__ldg(lpid + e), e);
    }
}

// ---------------- L6/L7: L2-blocked two-pass gather ----------------
// Pass 1: papers [0, HALF) — x lower half (~128 MB) is L2-resident. Partial sums
//         stored with streaming hint (no L2 pollution).
// Pass 2: papers [HALF, NP) — x upper half resident; add partial, divide, store avg.
// Branchless masking: out-of-range papers redirect to row `lo` (L1-hot) with mask 0,
// preserving the R7 4-deep load pipeline exactly.
__global__ void k_gather_pass(const float4* __restrict__ x, int lo, int hi, int last) {
    int w = (int)(((size_t)blockIdx.x * blockDim.x + threadIdx.x) >> 5);
    int lane = threadIdx.x & 31;
    if (w >= NA) return;
    int s = g_aoff[w];
    int e = (w + 1 < NA) ? g_aoff[w + 1] : NE;

    float4 a0 = make_float4(0.f, 0.f, 0.f, 0.f);
    float4 a1 = make_float4(0.f, 0.f, 0.f, 0.f);
    int i = s;
    for (; i + 4 <= e; i += 4) {
        int q0 = __ldcs(g_sp + i + 0);
        int q1 = __ldcs(g_sp + i + 1);
        int q2 = __ldcs(g_sp + i + 2);
        int q3 = __ldcs(g_sp + i + 3);
        bool m0 = (q0 >= lo) && (q0 < hi);
        bool m1 = (q1 >= lo) && (q1 < hi);
        bool m2 = (q2 >= lo) && (q2 < hi);
        bool m3 = (q3 >= lo) && (q3 < hi);
        int p0 = m0 ? q0 : lo;
        int p1 = m1 ? q1 : lo;
        int p2 = m2 ? q2 : lo;
        int p3 = m3 ? q3 : lo;
        float f0 = m0 ? 1.f : 0.f;
        float f1 = m1 ? 1.f : 0.f;
        float f2 = m2 ? 1.f : 0.f;
        float f3 = m3 ? 1.f : 0.f;
        float4 v0 = __ldg(x + (size_t)p0 * (HID / 4) + lane);
        float4 v1 = __ldg(x + (size_t)p1 * (HID / 4) + lane);
        float4 v2 = __ldg(x + (size_t)p2 * (HID / 4) + lane);
        float4 v3 = __ldg(x + (size_t)p3 * (HID / 4) + lane);
        a0.x += v0.x * f0 + v2.x * f2; a0.y += v0.y * f0 + v2.y * f2;
        a0.z += v0.z * f0 + v2.z * f2; a0.w += v0.w * f0 + v2.w * f2;
        a1.x += v1.x * f1 + v3.x * f3; a1.y += v1.y * f1 + v3.y * f3;
        a1.z += v1.z * f1 + v3.z * f3; a1.w += v1.w * f1 + v3.w * f3;
    }
    for (; i < e; i++) {
        int q = __ldcs(g_sp + i);
        if (q >= lo && q < hi) {
            float4 v = __ldg(x + (size_t)q * (HID / 4) + lane);
            a0.x += v.x; a0.y += v.y; a0.z += v.z; a0.w += v.w;
        }
    }
    float4 sum;
    sum.x = a0.x + a1.x; sum.y = a0.y + a1.y;
    sum.z = a0.z + a1.z; sum.w = a0.w + a1.w;
    float4* dst = reinterpret_cast<float4*>(g_acc) + (size_t)w * (HID / 4) + lane;
    if (!last) {
        __stcs(dst, sum);                 // raw partial (streaming: keep L2 for x)
    } else {
        float4 part = __ldcs(dst);        // read-once partial
        float inv = (e > s) ? (1.0f / (float)(e - s)) : 0.f;
        float4 r;
        r.x = (part.x + sum.x) * inv; r.y = (part.y + sum.y) * inv;
        r.z = (part.z + sum.z) * inv; r.w = (part.w + sum.w) * inv;
        __stcs(dst, r);                   // final avg (transform streams it later)
    }
}

// ---------------- L8: transform (R7-proven body, byte-identical) ----------------
__global__ void __launch_bounds__(128, 3) k_transform(int A) {
    __shared__ __align__(16) float s_avg[HID];
    __shared__ float s_red[4];
    int tid = threadIdx.x;

    unsigned long long Mc[HID / 2];  // (M[2k][tid], M[2k+1][tid])
#pragma unroll
    for (int kp = 0; kp < HID / 2; kp++)
        Mc[kp] = pack2(g_M[(2 * kp) * HID + tid], g_M[(2 * kp + 1) * HID + tid]);

    float u1 = g_u1[tid], u0 = g_u0[tid], v = g_v[tid];
    float c1 = g_c1c0[0], c0 = g_c1c0[1];

    int row = blockIdx.x;
    float aval_next = (row < A) ? g_acc[(size_t)row * HID + tid] : 0.f;
    for (; row < A; row += gridDim.x) {
        float aval = aval_next;
        int nrow = row + gridDim.x;
        if (nrow < A) aval_next = g_acc[(size_t)nrow * HID + tid];  // prefetch

        int rs = g_aoff[row];
        int re = (row + 1 < NA) ? g_aoff[row + 1] : NE;
        bool has = (re > rs);

        s_avg[tid] = aval;
        float pp = aval * v;
#pragma unroll
        for (int o = 16; o; o >>= 1) pp += __shfl_down_sync(0xffffffffu, pp, o);
        if ((tid & 31) == 0) s_red[tid >> 5] = pp;
        __syncthreads();

        unsigned long long acc2 = pack2(0.f, 0.f);
        const unsigned long long* avg2 = reinterpret_cast<const unsigned long long*>(s_avg);
#pragma unroll
        for (int kp = 0; kp < HID / 2; kp++)
            FMA_F32X2(acc2, avg2[kp], Mc[kp], acc2);
        float alo, ahi;
        unpack2(acc2, alo, ahi);
        float g = alo + ahi + (has ? u1 : u0);

        if (tid == 0)
            g_ac[row] = s_red[0] + s_red[1] + s_red[2] + s_red[3] + (has ? c1 : c0);
        __syncthreads();
        g_acc[(size_t)row * HID + tid] = g;  // in-place: becomes author_g
    }
}

// ---------------- L9: classifier (R7-proven body, byte-identical) ----------------
__global__ void k_classify(const float4* __restrict__ x, float* __restrict__ out) {
    int w = (int)(((size_t)blockIdx.x * blockDim.x + threadIdx.x) >> 5);
    int lane = threadIdx.x & 31;
    if (w >= NA) return;
    int s = g_loff[w];
    int e = (w + 1 < NA) ? g_loff[w + 1] : NL;
    if (s == e) return;
    float4 gv = reinterpret_cast<const float4*>(g_acc)[(size_t)w * (HID / 4) + lane];
    float ac = g_ac[w];
    int i = s;
    for (; i + 2 <= e; i += 2) {
        int2 pe0 = __ldg(g_slab + i);
        int2 pe1 = __ldg(g_slab + i + 1);
        float4 x0 = __ldg(x + (size_t)pe0.x * (HID / 4) + lane);
        float4 x1 = __ldg(x + (size_t)pe1.x * (HID / 4) + lane);
        float d0 = gv.x * x0.x + gv.y * x0.y + gv.z * x0.z + gv.w * x0.w;
        float d1 = gv.x * x1.x + gv.y * x1.y + gv.z * x1.z + gv.w * x1.w;
#pragma unroll
        for (int o = 16; o; o >>= 1) {
            d0 += __shfl_down_sync(0xffffffffu, d0, o);
            d1 += __shfl_down_sync(0xffffffffu, d1, o);
        }
        if (lane == 0) { out[pe0.y] = d0 + ac; out[pe1.y] = d1 + ac; }
    }
    if (i < e) {
        int2 pe = __ldg(g_slab + i);
        float4 xv = __ldg(x + (size_t)pe.x * (HID / 4) + lane);
        float d = gv.x * xv.x + gv.y * xv.y + gv.z * xv.z + gv.w * xv.w;
#pragma unroll
        for (int o = 16; o; o >>= 1) d += __shfl_down_sync(0xffffffffu, d, o);
        if (lane == 0) out[pe.y] = d + ac;
    }
}

// ---------------- launch: 9 launches ----------------
extern "C" void kernel_launch(void* const* d_in, const int* in_sizes, int n_in,
                              void* d_out, int out_size) {
    const float* paper_x = (const float*)d_in[0];
    const int* aid  = (const int*)d_in[1];
    const int* pid  = (const int*)d_in[2];
    const int* laid = (const int*)d_in[3];
    const int* lpid = (const int*)d_in[4];
    const float* Wp = (const float*)d_in[5];
    const float* bp = (const float*)d_in[6];
    const float* Wa = (const float*)d_in[7];
    const float* ba = (const float*)d_in[8];
    float* out = (float*)d_out;

    k_zero_prep1<<<ZERO_BLOCKS + HID, 256>>>(Wp, Wa);                       // 1
    k_hist_prep2<<<HIST_BLOCKS + HID + 1, 256>>>(aid, laid, Wp, bp, Wa, ba);// 2
    k_scan1_both<<<dim3(SCAN_NB, 2), 1024>>>();                             // 3
    k_scan23_both<<<dim3(SCAN_NB, 2), 1024>>>();                            // 4
    k_reorder<<<2048, 256>>>(aid, pid, laid, lpid);                         // 5
    k_gather_pass<<<(NA + 7) / 8, 256>>>((const float4*)paper_x,            // 6
                                         0, HALF, 0);
    k_gather_pass<<<(NA + 7) / 8, 256>>>((const float4*)paper_x,            // 7
                                         HALF, NP, 1);
    k_transform<<<444, 128>>>(NA);                                          // 8
    k_classify<<<(NA + 7) / 8, 256>>>((const float4*)paper_x, out);         // 9
}

// round 15
// speedup vs baseline: 1.1263x; 1.1263x over previous
#include <cuda_runtime.h>

// Problem constants (fixed by the dataset)
#define NA 200000          // num authors
#define NP 500000          // num papers
#define NE 2000000         // num writes-edges
#define NL 500000          // num label edges
#define HID 128

// ---------------- device scratch (static, no allocation) ----------------
__device__ float g_acc[(size_t)NA * HID];  // author avg-x -> reused as author_g
__device__ float g_ac[NA];                 // author_c scalar per author
__device__ float g_B[HID * HID];           // W_author @ W_paper^T
__device__ float g_M[HID * HID];           // W_paper @ B  (collapsed operator)
__device__ float g_u1[HID];
__device__ float g_u0[HID];
__device__ float g_v[HID];
__device__ float g_c1c0[2];

// edge sort (by author)
__device__ int g_acnt[NA];
__device__ int g_aoff[NA];
__device__ int g_acur[NA];
__device__ int g_sp[NE];

// label-edge sort (by author)
__device__ int g_lcnt[NA];
__device__ int g_loff[NA];
__device__ int g_lcur[NA];
__device__ int2 g_slab[NL];

// scan temporaries (device-side access only!)
__device__ int g_bsA[512];
__device__ int g_bpA[512];
__device__ int g_bsL[512];
__device__ int g_bpL[512];

// ---------------- packed f32x2 helpers ----------------
__device__ __forceinline__ unsigned long long pack2(float lo, float hi) {
    unsigned long long r;
    asm("mov.b64 %0, {%1, %2};" : "=l"(r) : "f"(lo), "f"(hi));
    return r;
}
__device__ __forceinline__ void unpack2(unsigned long long v, float& lo, float& hi) {
    asm("mov.b64 {%0, %1}, %2;" : "=f"(lo), "=f"(hi) : "l"(v));
}
#define FMA_F32X2(d, a, b, c) \
    asm("fma.rn.f32x2 %0, %1, %2, %3;" : "=l"(d) : "l"(a), "l"(b), "l"(c))

// ---------------- zero histograms ----------------
__global__ void k_zero() {
    int i = blockIdx.x * blockDim.x + threadIdx.x;
    int stride = gridDim.x * blockDim.x;
    for (int j = i; j < NA; j += stride) { g_acnt[j] = 0; g_lcnt[j] = 0; }
}

// ---------------- histograms ----------------
__global__ void k_hist(const int* __restrict__ aid, const int* __restrict__ laid) {
    int i = blockIdx.x * blockDim.x + threadIdx.x;
    int stride = gridDim.x * blockDim.x;
    for (int e = i; e < NE; e += stride)
        atomicAdd(&g_acnt[__ldg(aid + e)], 1);
    for (int e = i; e < NL; e += stride)
        atomicAdd(&g_lcnt[__ldg(laid + e)], 1);
}

// ---------------- two-level exclusive scan (device-side symbol binding ONLY) --------
// __device__ globals must never be passed as kernel args from host code (host
// shadow address != device address; ATS makes the bug silent).
__device__ __forceinline__ void scan1_body(const int* __restrict__ in, int* __restrict__ out,
                                           int* __restrict__ bsum, int n) {
    __shared__ int s[1024];
    int i = blockIdx.x * 1024 + threadIdx.x;
    int v = (i < n) ? in[i] : 0;
    s[threadIdx.x] = v;
    __syncthreads();
    for (int o = 1; o < 1024; o <<= 1) {
        int t = (threadIdx.x >= o) ? s[threadIdx.x - o] : 0;
        __syncthreads();
        s[threadIdx.x] += t;
        __syncthreads();
    }
    if (i < n) out[i] = s[threadIdx.x] - v;  // exclusive
    if (threadIdx.x == 1023) bsum[blockIdx.x] = s[1023];
}

__device__ __forceinline__ void scan2_body(const int* __restrict__ bsum,
                                           int* __restrict__ bpre, int nb) {
    __shared__ int s[512];
    int v = (threadIdx.x < nb) ? bsum[threadIdx.x] : 0;
    s[threadIdx.x] = v;
    __syncthreads();
    for (int o = 1; o < 512; o <<= 1) {
        int t = (threadIdx.x >= o) ? s[threadIdx.x - o] : 0;
        __syncthreads();
        s[threadIdx.x] += t;
        __syncthreads();
    }
    if (threadIdx.x < nb) bpre[threadIdx.x] = s[threadIdx.x] - v;  // exclusive
}

__device__ __forceinline__ void scan3_body(int* __restrict__ off, int* __restrict__ cur,
                                           const int* __restrict__ bpre, int n) {
    int i = blockIdx.x * 1024 + threadIdx.x;
    if (i < n) {
        int o = off[i] + bpre[blockIdx.x];
        off[i] = o;
        cur[i] = o;
    }
}

__global__ void k_scan1_a() { scan1_body(g_acnt, g_aoff, g_bsA, NA); }
__global__ void k_scan2_a(int nb) { scan2_body(g_bsA, g_bpA, nb); }
__global__ void k_scan3_a() { scan3_body(g_aoff, g_acur, g_bpA, NA); }

__global__ void k_scan1_l() { scan1_body(g_lcnt, g_loff, g_bsL, NA); }
__global__ void k_scan2_l(int nb) { scan2_body(g_bsL, g_bpL, nb); }
__global__ void k_scan3_l() { scan3_body(g_loff, g_lcur, g_bpL, NA); }

// ---------------- reorder edges by author / label edges by author ----------------
__global__ void k_reorder_e(const int* __restrict__ aid, const int* __restrict__ pid) {
    int i = blockIdx.x * blockDim.x + threadIdx.x;
    int stride = gridDim.x * blockDim.x;
    for (int e = i; e < NE; e += stride) {
        int a = __ldg(aid + e);
        int pos = atomicAdd(&g_acur[a], 1);
        g_sp[pos] = __ldg(pid + e);
    }
}

__global__ void k_reorder_l(const int* __restrict__ laid, const int* __restrict__ lpid) {
    int i = blockIdx.x * blockDim.x + threadIdx.x;
    int stride = gridDim.x * blockDim.x;
    for (int e = i; e < NL; e += stride) {
        int a = __ldg(laid + e);
        int pos = atomicAdd(&g_lcur[a], 1);
        g_slab[pos] = make_int2(__ldg(lpid + e), e);
    }
}

// ---------------- precompute step 1: B = W_author @ W_paper^T ----------------
__global__ void k_prep1(const float* __restrict__ Wp, const float* __restrict__ Wa) {
    __shared__ float wa[HID];
    int m = blockIdx.x;
    int j = threadIdx.x;
    wa[j] = Wa[m * HID + j];
    __syncthreads();
    float s = 0.f;
#pragma unroll 8
    for (int k = 0; k < HID; k++) s += wa[k] * Wp[j * HID + k];
    g_B[m * HID + j] = s;
}

// ---------------- precompute step 2: M = W_paper @ B, plus bias vectors ----------------
__global__ void k_prep2(const float* __restrict__ Wp, const float* __restrict__ bp,
                        const float* __restrict__ Wa, const float* __restrict__ ba) {
    int j = threadIdx.x;
    if (blockIdx.x < HID) {
        __shared__ float wp[HID];
        int i = blockIdx.x;
        wp[j] = Wp[i * HID + j];
        __syncthreads();
        float s = 0.f;
#pragma unroll 8
        for (int m = 0; m < HID; m++) s += wp[m] * g_B[m * HID + j];
        g_M[i * HID + j] = s;
    } else {
        __shared__ float w[HID];
        float s = 0.f;
        for (int k = 0; k < HID; k++) s += Wa[j * HID + k] * bp[k];
        w[j] = s;
        float u0 = 0.f;
        for (int k = 0; k < HID; k++) u0 += ba[k] * Wp[j * HID + k];
        g_u0[j] = u0;
        float u1 = u0;
        for (int m = 0; m < HID; m++) u1 += bp[m] * g_B[m * HID + j];
        g_u1[j] = u1;
        __syncthreads();
        float v = 0.f;
        for (int m = 0; m < HID; m++) v += Wp[j * HID + m] * w[m];
        g_v[j] = v;
        if (j == 0) {
            float c0 = 0.f;
            for (int k = 0; k < HID; k++) c0 += ba[k] * bp[k];
            float c1 = c0;
            for (int m = 0; m < HID; m++) c1 += bp[m] * w[m];
            g_c1c0[0] = c1;
            g_c1c0[1] = c0;
        }
    }
}

// ---------------- gather-average: warp per author (R7-proven body, byte-identical) ---
__global__ void k_gather_avg(const float4* __restrict__ x) {
    int w = (int)(((size_t)blockIdx.x * blockDim.x + threadIdx.x) >> 5);
    int lane = threadIdx.x & 31;
    if (w >= NA) return;
    int s = g_aoff[w];
    int e = (w + 1 < NA) ? g_aoff[w + 1] : NE;

    float4 a0 = make_float4(0.f, 0.f, 0.f, 0.f);
    float4 a1 = make_float4(0.f, 0.f, 0.f, 0.f);
    int i = s;
    for (; i + 4 <= e; i += 4) {
        int p0 = __ldg(g_sp + i + 0);
        int p1 = __ldg(g_sp + i + 1);
        int p2 = __ldg(g_sp + i + 2);
        int p3 = __ldg(g_sp + i + 3);
        float4 v0 = __ldg(x + (size_t)p0 * (HID / 4) + lane);
        float4 v1 = __ldg(x + (size_t)p1 * (HID / 4) + lane);
        float4 v2 = __ldg(x + (size_t)p2 * (HID / 4) + lane);
        float4 v3 = __ldg(x + (size_t)p3 * (HID / 4) + lane);
        a0.x += v0.x + v2.x; a0.y += v0.y + v2.y;
        a0.z += v0.z + v2.z; a0.w += v0.w + v2.w;
        a1.x += v1.x + v3.x; a1.y += v1.y + v3.y;
        a1.z += v1.z + v3.z; a1.w += v1.w + v3.w;
    }
    for (; i < e; i++) {
        int p = __ldg(g_sp + i);
        float4 v = __ldg(x + (size_t)p * (HID / 4) + lane);
        a0.x += v.x; a0.y += v.y; a0.z += v.z; a0.w += v.w;
    }
    float inv = (e > s) ? (1.0f / (float)(e - s)) : 0.f;
    float4 acc;
    acc.x = (a0.x + a1.x) * inv;
    acc.y = (a0.y + a1.y) * inv;
    acc.z = (a0.z + a1.z) * inv;
    acc.w = (a0.w + a1.w) * inv;
    reinterpret_cast<float4*>(g_acc)[(size_t)w * (HID / 4) + lane] = acc;
}

// ---------------- transform: R7 body + ping-pong smem (ONE barrier per row) ---------
// Safety of single barrier: iteration i reads buffer b after barrier_i; iteration
// i+1 writes buffer b^1 (disjoint); iteration i+2 rewrites buffer b only after
// barrier_{i+1}, which every reader of buffer b reached strictly after its reads.
__global__ void __launch_bounds__(128, 3) k_transform(int A) {
    __shared__ __align__(16) float s_avg[2][HID];
    __shared__ float s_red[2][4];
    int tid = threadIdx.x;

    unsigned long long Mc[HID / 2];  // (M[2k][tid], M[2k+1][tid])
#pragma unroll
    for (int kp = 0; kp < HID / 2; kp++)
        Mc[kp] = pack2(g_M[(2 * kp) * HID + tid], g_M[(2 * kp + 1) * HID + tid]);

    float u1 = g_u1[tid], u0 = g_u0[tid], v = g_v[tid];
    float c1 = g_c1c0[0], c0 = g_c1c0[1];

    int row = blockIdx.x;
    int b = 0;
    float aval_next = (row < A) ? g_acc[(size_t)row * HID + tid] : 0.f;
    for (; row < A; row += gridDim.x, b ^= 1) {
        float aval = aval_next;
        int nrow = row + gridDim.x;
        if (nrow < A) aval_next = g_acc[(size_t)nrow * HID + tid];  // prefetch

        int rs = g_aoff[row];
        int re = (row + 1 < NA) ? g_aoff[row + 1] : NE;
        bool has = (re > rs);

        s_avg[b][tid] = aval;
        float pp = aval * v;
#pragma unroll
        for (int o = 16; o; o >>= 1) pp += __shfl_down_sync(0xffffffffu, pp, o);
        if ((tid & 31) == 0) s_red[b][tid >> 5] = pp;
        __syncthreads();   // the ONLY barrier per row

        unsigned long long acc2 = pack2(0.f, 0.f);
        const unsigned long long* avg2 =
            reinterpret_cast<const unsigned long long*>(s_avg[b]);
#pragma unroll
        for (int kp = 0; kp < HID / 2; kp++)
            FMA_F32X2(acc2, avg2[kp], Mc[kp], acc2);
        float alo, ahi;
        unpack2(acc2, alo, ahi);
        float g = alo + ahi + (has ? u1 : u0);

        if (tid == 0)
            g_ac[row] = s_red[b][0] + s_red[b][1] + s_red[b][2] + s_red[b][3]
                        + (has ? c1 : c0);
        g_acc[(size_t)row * HID + tid] = g;  // in-place: becomes author_g
    }
}

// ---------------- classifier: warp per author, 2-wide (R7-proven body) ----------------
__global__ void k_classify(const float4* __restrict__ x, float* __restrict__ out) {
    int w = (int)(((size_t)blockIdx.x * blockDim.x + threadIdx.x) >> 5);
    int lane = threadIdx.x & 31;
    if (w >= NA) return;
    int s = g_loff[w];
    int e = (w + 1 < NA) ? g_loff[w + 1] : NL;
    if (s == e) return;
    float4 gv = reinterpret_cast<const float4*>(g_acc)[(size_t)w * (HID / 4) + lane];
    float ac = g_ac[w];
    int i = s;
    for (; i + 2 <= e; i += 2) {
        int2 pe0 = __ldg(g_slab + i);
        int2 pe1 = __ldg(g_slab + i + 1);
        float4 x0 = __ldg(x + (size_t)pe0.x * (HID / 4) + lane);
        float4 x1 = __ldg(x + (size_t)pe1.x * (HID / 4) + lane);
        float d0 = gv.x * x0.x + gv.y * x0.y + gv.z * x0.z + gv.w * x0.w;
        float d1 = gv.x * x1.x + gv.y * x1.y + gv.z * x1.z + gv.w * x1.w;
#pragma unroll
        for (int o = 16; o; o >>= 1) {
            d0 += __shfl_down_sync(0xffffffffu, d0, o);
            d1 += __shfl_down_sync(0xffffffffu, d1, o);
        }
        if (lane == 0) { out[pe0.y] = d0 + ac; out[pe1.y] = d1 + ac; }
    }
    if (i < e) {
        int2 pe = __ldg(g_slab + i);
        float4 xv = __ldg(x + (size_t)pe.x * (HID / 4) + lane);
        float d = gv.x * xv.x + gv.y * xv.y + gv.z * xv.z + gv.w * xv.w;
#pragma unroll
        for (int o = 16; o; o >>= 1) d += __shfl_down_sync(0xffffffffu, d, o);
        if (lane == 0) out[pe.y] = d + ac;
    }
}

// ---------------- launch (R7-exact chain) ----------------
extern "C" void kernel_launch(void* const* d_in, const int* in_sizes, int n_in,
                              void* d_out, int out_size) {
    const float* paper_x = (const float*)d_in[0];
    const int* aid  = (const int*)d_in[1];
    const int* pid  = (const int*)d_in[2];
    const int* laid = (const int*)d_in[3];
    const int* lpid = (const int*)d_in[4];
    const float* Wp = (const float*)d_in[5];
    const float* bp = (const float*)d_in[6];
    const float* Wa = (const float*)d_in[7];
    const float* ba = (const float*)d_in[8];
    float* out = (float*)d_out;

    k_zero<<<512, 256>>>();
    k_hist<<<2048, 256>>>(aid, laid);

    {
        int nb = (NA + 1023) / 1024;
        k_scan1_a<<<nb, 1024>>>();
        k_scan2_a<<<1, 512>>>(nb);
        k_scan3_a<<<nb, 1024>>>();
        k_scan1_l<<<nb, 1024>>>();
        k_scan2_l<<<1, 512>>>(nb);
        k_scan3_l<<<nb, 1024>>>();
    }

    k_reorder_e<<<2048, 256>>>(aid, pid);
    k_reorder_l<<<1024, 256>>>(laid, lpid);

    k_prep1<<<HID, HID>>>(Wp, Wa);
    k_prep2<<<HID + 1, HID>>>(Wp, bp, Wa, ba);

    k_gather_avg<<<(NA + 7) / 8, 256>>>((const float4*)paper_x);
    k_transform<<<444, 128>>>(NA);
    k_classify<<<(NA + 7) / 8, 256>>>((const float4*)paper_x, out);
}